// round 17
// baseline (speedup 1.0000x reference)
#include <cuda_runtime.h>
#include <cuda_fp16.h>
#include <math.h>

#define N_NODES 100000
#define N_EV    200000
#define N_SEDGE 1600000
#define SCHUNK  1024
#define SNBLK   ((N_NODES + SCHUNK - 1) / SCHUNK)

/* ---------------- device scratch (no allocations allowed) ---------------- */
__device__ __align__(16) int    g_last[N_NODES];
__device__ __align__(16) __half g_xh  [N_NODES * 128];
__device__ __align__(16) float  g_as  [N_NODES];
__device__ __align__(16) float  g_ad  [N_NODES];
__device__ __align__(16) int    g_cnt [N_NODES];
__device__ __align__(16) int    g_off [N_NODES];
__device__ __align__(16) int    g_pos [N_NODES];
__device__               int    g_part[SNBLK];
__device__ __align__(16) int    g_csrs[N_SEDGE];

/* ---------------- fp16 MMA helpers (m16n8k16, f32 accum) ---------------- */
__device__ __forceinline__ unsigned h2pk(float a, float b) {
    __half2 h = __floats2half2_rn(a, b);
    return *(unsigned*)&h;
}
__device__ __forceinline__ void mma16(float (&c)[4], unsigned a0, unsigned a1,
                                      unsigned a2, unsigned a3,
                                      unsigned b0, unsigned b1) {
    asm("mma.sync.aligned.m16n8k16.row.col.f32.f16.f16.f32 "
        "{%0,%1,%2,%3},{%4,%5,%6,%7},{%8,%9},{%0,%1,%2,%3};"
        : "+f"(c[0]), "+f"(c[1]), "+f"(c[2]), "+f"(c[3])
        : "r"(a0), "r"(a1), "r"(a2), "r"(a3), "r"(b0), "r"(b1));
}
__device__ __forceinline__ float fsig(float x) {
    return __fdividef(1.f, 1.f + __expf(-x));
}
__device__ __forceinline__ float ftanh_(float x) {
    return 1.f - __fdividef(2.f, __expf(2.f * x) + 1.f);
}
__device__ __forceinline__ float fsig_r(float x) {
    float y; asm("tanh.approx.f32 %0,%1;" : "=f"(y) : "f"(x * 0.5f));
    return fmaf(0.5f, y, 0.5f);
}

/* ---------------- init ---------------- */
__global__ void k_init_last() {
    int i = blockIdx.x * blockDim.x + threadIdx.x;
    if (i < N_NODES) g_last[i] = -1;
}
__global__ void k_init_cnt() {
    int i = blockIdx.x * blockDim.x + threadIdx.x;
    if (i < N_NODES) g_cnt[i] = 0;
}

/* ---------------- last event per node ---------------- */
__global__ void k_last(const int* __restrict__ src, const int* __restrict__ dst) {
    int i = blockIdx.x * blockDim.x + threadIdx.x;
    if (i >= N_EV) return;
    atomicMax(&g_last[src[i]], i);
    atomicMax(&g_last[dst[i]], i);
}

/* ---------------- CSR build: count / scan / fill ---------------- */
__global__ void k_count(const int* __restrict__ ed) {
    int i = blockIdx.x * blockDim.x + threadIdx.x;
    if (i < N_SEDGE) atomicAdd(&g_cnt[ed[i]], 1);
}

__global__ void k_scanA() {
    int b = blockIdx.x, t = threadIdx.x;
    int base = b * SCHUNK + t * 4;
    int s = 0;
#pragma unroll
    for (int u = 0; u < 4; u++) { int i = base + u; if (i < N_NODES) s += g_cnt[i]; }
#pragma unroll
    for (int o = 16; o; o >>= 1) s += __shfl_xor_sync(0xFFFFFFFFu, s, o);
    __shared__ int ws[8];
    if ((t & 31) == 0) ws[t >> 5] = s;
    __syncthreads();
    if (t == 0) { int tot = 0; for (int w = 0; w < 8; w++) tot += ws[w]; g_part[b] = tot; }
}

__global__ void k_scanB() {
    int t = threadIdx.x;
    int v = (t < SNBLK) ? g_part[t] : 0;
    int lane = t & 31, wid = t >> 5;
    int inc = v;
#pragma unroll
    for (int o = 1; o < 32; o <<= 1) { int n = __shfl_up_sync(0xFFFFFFFFu, inc, o); if (lane >= o) inc += n; }
    __shared__ int ws[4];
    if (lane == 31) ws[wid] = inc;
    __syncthreads();
    if (t == 0) { int r = 0; for (int i = 0; i < 4; i++) { int x = ws[i]; ws[i] = r; r += x; } }
    __syncthreads();
    if (t < SNBLK) g_part[t] = inc - v + ws[wid];
}

__global__ void k_scanC() {
    int b = blockIdx.x, t = threadIdx.x;
    int base = b * SCHUNK + t * 4;
    int c[4]; int s = 0;
#pragma unroll
    for (int u = 0; u < 4; u++) { int i = base + u; c[u] = (i < N_NODES) ? g_cnt[i] : 0; s += c[u]; }
    int lane = t & 31, wid = t >> 5;
    int inc = s;
#pragma unroll
    for (int o = 1; o < 32; o <<= 1) { int n = __shfl_up_sync(0xFFFFFFFFu, inc, o); if (lane >= o) inc += n; }
    __shared__ int ws[8];
    if (lane == 31) ws[wid] = inc;
    __syncthreads();
    if (t == 0) { int r = 0; for (int i = 0; i < 8; i++) { int x = ws[i]; ws[i] = r; r += x; } }
    __syncthreads();
    int off = g_part[b] + ws[wid] + inc - s;
#pragma unroll
    for (int u = 0; u < 4; u++) {
        int i = base + u;
        if (i < N_NODES) { g_off[i] = off; g_pos[i] = off; }
        off += c[u];
    }
}

__global__ void k_fill(const int* __restrict__ es, const int* __restrict__ ed) {
    int i = blockIdx.x * blockDim.x + threadIdx.x;
    if (i >= N_SEDGE) return;
    int pos = atomicAdd(&g_pos[ed[i]], 1);
    g_csrs[pos] = es[i];
}

/* ---------------- FUSED GRU + GAT projection + attention scores -------------- */
#define GRU_WENT (8 * 6 * 32 * 6)    /* uint2 = 73728 B */
#define XW_ENT   (8 * 2 * 32 * 10)   /* uint2 = 40960 B */
__global__ void __launch_bounds__(512, 1)
k_grux(const int* __restrict__ t, const float* __restrict__ msg,
       const float* __restrict__ w_ih, const float* __restrict__ b_ih,
       const float* __restrict__ b_hh,
       const float* __restrict__ time_w, const float* __restrict__ time_b,
       const float* __restrict__ gat_w, const float* __restrict__ att_src,
       const float* __restrict__ att_dst) {
    extern __shared__ unsigned smu[];
    uint2* GWf = (uint2*)smu;                  /* [p][k16][lane][t6] */
    uint2* XWf = GWf + GRU_WENT;               /* [k16][h][lane][n8(+pad)] */
    float* Bsm = (float*)(XWf + XW_ENT);       /* gate biases 4*128 */
    float* Tw  = Bsm + 512;
    float* Tb  = Tw + 32;
    float* Asm = Tb + 32;                      /* att_src[128], att_dst[128] */
    const int tid = threadIdx.x;

    for (int i = tid; i < GRU_WENT; i += 512) {
        int t6 = i % 6;
        int lane = (i / 6) & 31;
        int k16 = (i / 192) % 6;
        int p  = i / 1152;
        int g = t6 >> 1, jj = t6 & 1;
        int n8 = g * 16 + p * 2 + jj;
        int n = n8 * 8 + (lane >> 2);
        int k0 = k16 * 16 + 2 * (lane & 3);
        const float* wr = w_ih + n * 352 + 256;
        GWf[i] = make_uint2(h2pk(wr[k0], wr[k0 + 1]), h2pk(wr[k0 + 8], wr[k0 + 9]));
    }
    for (int i = tid; i < XW_ENT; i += 512) {
        int n8 = i % 10;
        int lane = (i / 10) & 31;
        int h = (i / 320) & 1;
        int k16 = i / 640;
        uint2 v = make_uint2(0u, 0u);
        if (n8 < 8) {
            int n = (h * 8 + n8) * 8 + (lane >> 2);
            int k0 = k16 * 16 + 2 * (lane & 3);
            const float* wr = gat_w + n * 128;
            v = make_uint2(h2pk(wr[k0], wr[k0 + 1]), h2pk(wr[k0 + 8], wr[k0 + 9]));
        }
        XWf[i] = v;
    }
    for (int k = tid; k < 128; k += 512) {
        Bsm[k]       = b_ih[k]       + b_hh[k];
        Bsm[128 + k] = b_ih[128 + k] + b_hh[128 + k];
        Bsm[256 + k] = b_ih[256 + k];
        Bsm[384 + k] = b_hh[256 + k];
    }
    if (tid < 32) { Tw[tid] = time_w[tid]; Tb[tid] = time_b[tid]; }
    if (tid < 256) Asm[tid] = (tid < 128) ? att_src[tid] : att_dst[tid - 128];
    __syncthreads();

    const int warp = tid >> 5, lane = tid & 31;
    const int grp = lane >> 2, tg = lane & 3;
    const int nwarps = gridDim.x * 16;

    for (int rg = blockIdx.x * 16 + warp; rg < N_NODES / 16; rg += nwarps) {
        const int node0 = rg * 16 + grp, node1 = node0 + 8;
        const int le0 = g_last[node0], le1 = g_last[node1];
        const bool h0 = le0 >= 0, h1 = le1 >= 0;
        const int e0 = h0 ? le0 : 0, e1 = h1 ? le1 : 0;
        const float tf0 = (float)t[e0];
        const float tf1 = (float)t[e1];
        const float* m0 = msg + (long)e0 * 64;
        const float* m1 = msg + (long)e1 * 64;

        unsigned a[6][4];
#pragma unroll
        for (int s = 0; s < 4; s++) {
            int k0 = s * 16 + 2 * tg;
            float2 v;
            v = __ldg((const float2*)(m0 + k0));     a[s][0] = h2pk(v.x, v.y);
            v = __ldg((const float2*)(m1 + k0));     a[s][1] = h2pk(v.x, v.y);
            v = __ldg((const float2*)(m0 + k0 + 8)); a[s][2] = h2pk(v.x, v.y);
            v = __ldg((const float2*)(m1 + k0 + 8)); a[s][3] = h2pk(v.x, v.y);
        }
#pragma unroll
        for (int s = 4; s < 6; s++) {
            int j0 = (s - 4) * 16 + 2 * tg;
            float wA = Tw[j0], bA = Tb[j0], wB = Tw[j0 + 1], bB = Tb[j0 + 1];
            float wC = Tw[j0 + 8], bC = Tb[j0 + 8], wD = Tw[j0 + 9], bD = Tb[j0 + 9];
            a[s][0] = h2pk(cosf(__fadd_rn(__fmul_rn(tf0, wA), bA)),
                           cosf(__fadd_rn(__fmul_rn(tf0, wB), bB)));
            a[s][1] = h2pk(cosf(__fadd_rn(__fmul_rn(tf1, wA), bA)),
                           cosf(__fadd_rn(__fmul_rn(tf1, wB), bB)));
            a[s][2] = h2pk(cosf(__fadd_rn(__fmul_rn(tf0, wC), bC)),
                           cosf(__fadd_rn(__fmul_rn(tf0, wD), bD)));
            a[s][3] = h2pk(cosf(__fadd_rn(__fmul_rn(tf1, wC), bC)),
                           cosf(__fadd_rn(__fmul_rn(tf1, wD), bD)));
        }

        unsigned a2[8][4];
#pragma unroll 1
        for (int p = 0; p < 8; p++) {
            float acc[6][4];
#pragma unroll
            for (int q = 0; q < 6; q++)
#pragma unroll
                for (int i = 0; i < 4; i++) acc[q][i] = 0.f;

#pragma unroll
            for (int k16 = 0; k16 < 6; k16++) {
                const uint4* wp = (const uint4*)(GWf + ((p * 6 + k16) * 32 + lane) * 6);
                uint4 w0 = wp[0], w1 = wp[1], w2 = wp[2];
                mma16(acc[0], a[k16][0], a[k16][1], a[k16][2], a[k16][3], w0.x, w0.y);
                mma16(acc[1], a[k16][0], a[k16][1], a[k16][2], a[k16][3], w0.z, w0.w);
                mma16(acc[2], a[k16][0], a[k16][1], a[k16][2], a[k16][3], w1.x, w1.y);
                mma16(acc[3], a[k16][0], a[k16][1], a[k16][2], a[k16][3], w1.z, w1.w);
                mma16(acc[4], a[k16][0], a[k16][1], a[k16][2], a[k16][3], w2.x, w2.y);
                mma16(acc[5], a[k16][0], a[k16][1], a[k16][2], a[k16][3], w2.z, w2.w);
            }
#pragma unroll
            for (int jj = 0; jj < 2; jj++) {
                int kbase = (p * 2 + jj) * 8 + 2 * tg;
                float o0[2], o1[2];
#pragma unroll
                for (int ii = 0; ii < 2; ii++) {
                    int kk = kbase + ii;
                    float br = Bsm[kk], bz = Bsm[128 + kk];
                    float bin = Bsm[256 + kk], bhn = Bsm[384 + kk];
                    {
                        float r = fsig_r(acc[jj][ii] + br);
                        float z = fsig(acc[2 + jj][ii] + bz);
                        float nn = ftanh_(acc[4 + jj][ii] + bin + r * bhn);
                        o0[ii] = h0 ? (1.f - z) * nn : 0.f;
                    }
                    {
                        float r = fsig_r(acc[jj][2 + ii] + br);
                        float z = fsig(acc[2 + jj][2 + ii] + bz);
                        float nn = ftanh_(acc[4 + jj][2 + ii] + bin + r * bhn);
                        o1[ii] = h1 ? (1.f - z) * nn : 0.f;
                    }
                }
                a2[p][jj * 2]     = h2pk(o0[0], o0[1]);
                a2[p][jj * 2 + 1] = h2pk(o1[0], o1[1]);
            }
        }

        float ps0 = 0.f, pd0 = 0.f, ps1 = 0.f, pd1 = 0.f;
#pragma unroll 1
        for (int h = 0; h < 2; h++) {
            float acc[8][4];
#pragma unroll
            for (int q = 0; q < 8; q++)
#pragma unroll
                for (int i = 0; i < 4; i++) acc[q][i] = 0.f;

#pragma unroll
            for (int k16 = 0; k16 < 8; k16++) {
                const uint4* wp = (const uint4*)(XWf + ((k16 * 2 + h) * 32 + lane) * 10);
                uint4 wa = wp[0], wb = wp[1], wc = wp[2], wd = wp[3];
                mma16(acc[0], a2[k16][0], a2[k16][1], a2[k16][2], a2[k16][3], wa.x, wa.y);
                mma16(acc[1], a2[k16][0], a2[k16][1], a2[k16][2], a2[k16][3], wa.z, wa.w);
                mma16(acc[2], a2[k16][0], a2[k16][1], a2[k16][2], a2[k16][3], wb.x, wb.y);
                mma16(acc[3], a2[k16][0], a2[k16][1], a2[k16][2], a2[k16][3], wb.z, wb.w);
                mma16(acc[4], a2[k16][0], a2[k16][1], a2[k16][2], a2[k16][3], wc.x, wc.y);
                mma16(acc[5], a2[k16][0], a2[k16][1], a2[k16][2], a2[k16][3], wc.z, wc.w);
                mma16(acc[6], a2[k16][0], a2[k16][1], a2[k16][2], a2[k16][3], wd.x, wd.y);
                mma16(acc[7], a2[k16][0], a2[k16][1], a2[k16][2], a2[k16][3], wd.z, wd.w);
            }
#pragma unroll
            for (int n8 = 0; n8 < 8; n8++) {
                int col = (h * 8 + n8) * 8 + 2 * tg;
                float s0 = Asm[col], s1 = Asm[col + 1];
                float d0 = Asm[128 + col], d1 = Asm[128 + col + 1];
                ps0 += acc[n8][0] * s0 + acc[n8][1] * s1;
                pd0 += acc[n8][0] * d0 + acc[n8][1] * d1;
                ps1 += acc[n8][2] * s0 + acc[n8][3] * s1;
                pd1 += acc[n8][2] * d0 + acc[n8][3] * d1;
                *(__half2*)&g_xh[(long)node0 * 128 + col] =
                    __floats2half2_rn(acc[n8][0], acc[n8][1]);
                *(__half2*)&g_xh[(long)node1 * 128 + col] =
                    __floats2half2_rn(acc[n8][2], acc[n8][3]);
            }
        }
#pragma unroll
        for (int o = 1; o <= 2; o <<= 1) {
            ps0 += __shfl_xor_sync(0xFFFFFFFFu, ps0, o);
            pd0 += __shfl_xor_sync(0xFFFFFFFFu, pd0, o);
            ps1 += __shfl_xor_sync(0xFFFFFFFFu, ps1, o);
            pd1 += __shfl_xor_sync(0xFFFFFFFFu, pd1, o);
        }
        if (tg == 0) {
            g_as[node0] = ps0; g_ad[node0] = pd0;
            g_as[node1] = ps1; g_ad[node1] = pd1;
        }
    }
}

/* ---------------- FUSED GAT softmax+aggregation + ReLU + classifier ----------
 * Warp per 16-node rowgroup: 16 sequential warp-cooperative aggregations
 * stage relu(z+gat_b) as fp16 in smem (stride 136 halves: fragment reads are
 * bank-conflict-free), then the m16n8k16 classifier GEMM reads fragments
 * straight from staging. g_z roundtrip (102 MB) and one launch eliminated;
 * rounding path identical to the previous split kernels.
 */
#define CW_ENT (8 * 32 * 10)   /* uint2 = 20480 B */
#define SZ_STR 136             /* halves per staged row */
__global__ void __launch_bounds__(512, 1)
k_aggcls(const float* __restrict__ cls_w, const float* __restrict__ cls_b,
         const float* __restrict__ gat_b, float* __restrict__ out) {
    extern __shared__ unsigned smu[];
    uint2*  Wf  = (uint2*)smu;              /* [k16][lane][n8(+pad)] */
    float*  Cb  = (float*)(Wf + CW_ENT);
    float*  Gb  = Cb + 64;
    __half* Zst = (__half*)(Gb + 128);      /* [16 warps][16 rows][136] */
    const int tid = threadIdx.x;

    for (int i = tid; i < CW_ENT; i += 512) {
        int n8 = i % 10;
        int lane = (i / 10) & 31;
        int k16 = i / 320;
        uint2 v = make_uint2(0u, 0u);
        if (n8 < 8) {
            int n = n8 * 8 + (lane >> 2);
            int k0 = k16 * 16 + 2 * (lane & 3);
            const float* wr = cls_w + n * 128;
            v = make_uint2(h2pk(wr[k0], wr[k0 + 1]), h2pk(wr[k0 + 8], wr[k0 + 9]));
        }
        Wf[i] = v;
    }
    if (tid < 64) Cb[tid] = cls_b[tid];
    if (tid < 128) Gb[tid] = gat_b[tid];
    __syncthreads();

    const int warp = tid >> 5, lane = tid & 31;
    const int grp = lane >> 2, tg = lane & 3;
    const int nwarps = gridDim.x * 16;
    __half* myZ = Zst + warp * 16 * SZ_STR;
    const float gb0 = Gb[lane * 4], gb1 = Gb[lane * 4 + 1];
    const float gb2 = Gb[lane * 4 + 2], gb3 = Gb[lane * 4 + 3];

    for (int rg = blockIdx.x * 16 + warp; rg < N_NODES / 16; rg += nwarps) {
        /* ---- 16 warp-cooperative aggregations into fp16 staging ---- */
        for (int ni = 0; ni < 16; ni++) {
            int node = rg * 16 + ni;
            const int start = g_off[node], end = g_pos[node];
            const float ad = g_ad[node];
            float e_self = g_as[node] + ad;
            e_self = (e_self > 0.f) ? e_self : 0.2f * e_self;

            const float w0 = __expf(e_self);
            uint2 raw = __ldg((const uint2*)(g_xh + (long)node * 128) + lane);
            float2 lo = __half22float2(*(__half2*)&raw.x);
            float2 hi = __half22float2(*(__half2*)&raw.y);
            float4 acc = make_float4(w0 * lo.x, w0 * lo.y, w0 * hi.x, w0 * hi.y);
            float den_l = 0.f;

            for (int b = start; b < end; b += 32) {
                int rem = end - b;
                int n = rem < 32 ? rem : 32;
                int  s_l = 0;
                float w_l = 0.f;
                if (lane < n) {
                    s_l = __ldg(&g_csrs[b + lane]);
                    float e = __ldg(&g_as[s_l]) + ad;
                    e = (e > 0.f) ? e : 0.2f * e;
                    w_l = __expf(e);
                    den_l += w_l;
                }
#pragma unroll 4
                for (int j = 0; j < n; j++) {
                    int   s = __shfl_sync(0xFFFFFFFFu, s_l, j);
                    float w = __shfl_sync(0xFFFFFFFFu, w_l, j);
                    uint2 r = __ldg((const uint2*)(g_xh + (long)s * 128) + lane);
                    float2 l2 = __half22float2(*(__half2*)&r.x);
                    float2 h2 = __half22float2(*(__half2*)&r.y);
                    acc.x += w * l2.x; acc.y += w * l2.y;
                    acc.z += w * h2.x; acc.w += w * h2.y;
                }
            }
#pragma unroll
            for (int o = 16; o; o >>= 1) den_l += __shfl_xor_sync(0xFFFFFFFFu, den_l, o);
            float inv = 1.f / (den_l + w0);
            float v0 = fmaxf(acc.x * inv + gb0, 0.f);
            float v1 = fmaxf(acc.y * inv + gb1, 0.f);
            float v2 = fmaxf(acc.z * inv + gb2, 0.f);
            float v3 = fmaxf(acc.w * inv + gb3, 0.f);
            __half* zr = myZ + ni * SZ_STR + lane * 4;
            *(__half2*)zr       = __floats2half2_rn(v0, v1);
            *(__half2*)(zr + 2) = __floats2half2_rn(v2, v3);
        }
        __syncwarp();

        /* ---- classifier GEMM from staging ---- */
        unsigned a[8][4];
#pragma unroll
        for (int s = 0; s < 8; s++) {
            int k0 = s * 16 + 2 * tg;
            a[s][0] = *(unsigned*)&myZ[grp * SZ_STR + k0];
            a[s][1] = *(unsigned*)&myZ[(grp + 8) * SZ_STR + k0];
            a[s][2] = *(unsigned*)&myZ[grp * SZ_STR + k0 + 8];
            a[s][3] = *(unsigned*)&myZ[(grp + 8) * SZ_STR + k0 + 8];
        }

        float acc[8][4];
#pragma unroll
        for (int q = 0; q < 8; q++)
#pragma unroll
            for (int i = 0; i < 4; i++) acc[q][i] = 0.f;

#pragma unroll
        for (int k16 = 0; k16 < 8; k16++) {
            const uint4* wp = (const uint4*)(Wf + (k16 * 32 + lane) * 10);
            uint4 wa = wp[0], wb = wp[1], wc = wp[2], wd = wp[3];
            mma16(acc[0], a[k16][0], a[k16][1], a[k16][2], a[k16][3], wa.x, wa.y);
            mma16(acc[1], a[k16][0], a[k16][1], a[k16][2], a[k16][3], wa.z, wa.w);
            mma16(acc[2], a[k16][0], a[k16][1], a[k16][2], a[k16][3], wb.x, wb.y);
            mma16(acc[3], a[k16][0], a[k16][1], a[k16][2], a[k16][3], wb.z, wb.w);
            mma16(acc[4], a[k16][0], a[k16][1], a[k16][2], a[k16][3], wc.x, wc.y);
            mma16(acc[5], a[k16][0], a[k16][1], a[k16][2], a[k16][3], wc.z, wc.w);
            mma16(acc[6], a[k16][0], a[k16][1], a[k16][2], a[k16][3], wd.x, wd.y);
            mma16(acc[7], a[k16][0], a[k16][1], a[k16][2], a[k16][3], wd.z, wd.w);
        }
        int node0 = rg * 16 + grp, node1 = node0 + 8;
#pragma unroll
        for (int n8 = 0; n8 < 8; n8++) {
            int col = n8 * 8 + 2 * tg;
            float b0 = Cb[col], b1 = Cb[col + 1];
            *(float2*)&out[(long)node0 * 64 + col] =
                make_float2(acc[n8][0] + b0, acc[n8][1] + b1);
            *(float2*)&out[(long)node1 * 64 + col] =
                make_float2(acc[n8][2] + b0, acc[n8][3] + b1);
        }
        __syncwarp();
    }
}

/* ---------------- launch ----------------
 * Fork-join: CSR build overlapped on a side stream; joined before k_aggcls.
 * Host issue order keeps k_grux as the 4th kernel for the ncu window.
 */
extern "C" void kernel_launch(void* const* d_in, const int* in_sizes, int n_in,
                              void* d_out, int out_size) {
    const int*   src    = (const int*)  d_in[0];
    const int*   dst    = (const int*)  d_in[1];
    const int*   t      = (const int*)  d_in[2];
    const float* msg    = (const float*)d_in[3];
    const int*   sei    = (const int*)  d_in[4];
    const float* time_w = (const float*)d_in[5];
    const float* time_b = (const float*)d_in[6];
    const float* w_ih   = (const float*)d_in[7];
    /* d_in[8] = gru_w_hh: unused (memory == 0 at update time) */
    const float* b_ih   = (const float*)d_in[9];
    const float* b_hh   = (const float*)d_in[10];
    const float* gat_w  = (const float*)d_in[11];
    const float* att_s  = (const float*)d_in[12];
    const float* att_d  = (const float*)d_in[13];
    const float* gat_b  = (const float*)d_in[14];
    const float* cls_w  = (const float*)d_in[15];
    const float* cls_b  = (const float*)d_in[16];
    float* out = (float*)d_out;
    const int* es = sei;
    const int* ed = sei + N_SEDGE;
    (void)in_sizes; (void)n_in; (void)out_size;

    static cudaStream_t s1 = 0;
    static cudaEvent_t evRoot = 0, evSide = 0;
    static int ok = -1;
    if (ok < 0) {
        ok = 1;
        if (cudaStreamCreateWithFlags(&s1, cudaStreamNonBlocking) != cudaSuccess) ok = 0;
        if (ok && cudaEventCreateWithFlags(&evRoot, cudaEventDisableTiming) != cudaSuccess) ok = 0;
        if (ok && cudaEventCreateWithFlags(&evSide, cudaEventDisableTiming) != cudaSuccess) ok = 0;
    }
    cudaStream_t sC = ok ? s1 : 0;

    if (ok) { cudaEventRecord(evRoot, 0); cudaStreamWaitEvent(s1, evRoot, 0); }

    k_init_last<<<(N_NODES + 255) / 256, 256>>>();
    k_last     <<<(N_EV + 255) / 256, 256>>>(src, dst);
    k_init_cnt <<<(N_NODES + 255) / 256, 256, 0, sC>>>();

    {
        size_t smb = (size_t)(GRU_WENT + XW_ENT) * 8 + (512 + 64 + 256) * 4;
        cudaFuncSetAttribute(k_grux, cudaFuncAttributeMaxDynamicSharedMemorySize, (int)smb);
        k_grux<<<148, 512, smb>>>(t, msg, w_ih, b_ih, b_hh, time_w, time_b,
                                  gat_w, att_s, att_d);
    }

    k_count<<<(N_SEDGE + 255) / 256, 256, 0, sC>>>(ed);
    k_scanA<<<SNBLK, 256, 0, sC>>>();
    k_scanB<<<1, 128, 0, sC>>>();
    k_scanC<<<SNBLK, 256, 0, sC>>>();
    k_fill <<<(N_SEDGE + 255) / 256, 256, 0, sC>>>(es, ed);
    if (ok) cudaEventRecord(evSide, s1);

    if (ok) cudaStreamWaitEvent(0, evSide, 0);
    {
        size_t smb = (size_t)CW_ENT * 8 + 192 * 4
                   + (size_t)16 * 16 * SZ_STR * 2;
        cudaFuncSetAttribute(k_aggcls, cudaFuncAttributeMaxDynamicSharedMemorySize, (int)smb);
        k_aggcls<<<148, 512, smb>>>(cls_w, cls_b, gat_b, out);
    }
}